// round 13
// baseline (speedup 1.0000x reference)
#include <cuda_runtime.h>

// GradPooling: fused 2x2 stride-2 max/avg pool gated by local gradient vs lamb.
// x: (32, 224, 224, 64) f32 NHWC ; lamb: (1,) ; out: (32, 112, 112, 64) f32
//
// out[b,oi,oj,c] = sel ? max2x2 : avg2x2 over zero-padded x window
//   window rows {2oi-1, 2oi}, cols {2oj-1, 2oj}  (pad value 0)
// sel = 2*(|a-u| + |a-l|) > lamb, with
//   a = x[b, oi+1, oj+1, c], u = x[b, oi, oj+1, c], l = x[b, oi+1, oj, c]
//
// R13: R6 per-thread code UNCHANGED (best: 78.3us, DRAM ~82%). Only the grid
// dimension order is permuted: b on blockIdx.x (fastest) instead of slowest.
// Concurrent CTAs now spread across all 32 batch images -> reads fan out over
// 32 disjoint ~1MB windows (better LTS-slice / DRAM-channel spreading) instead
// of one ~27MB contiguous window. SASS schedule identical to R6.

#define BB 32
#define HH 224
#define WW 224
#define CC 64
#define OH 112
#define OW 112
#define C4 16   // CC/4 float4 lanes per pixel

__global__ __launch_bounds__(128) void gradpool_kernel(
    const float4* __restrict__ x4,
    const float* __restrict__ lamb,
    float4* __restrict__ out4)
{
    const int tx  = threadIdx.x;
    const int c4  = tx & 15;                 // channel float4 lane
    const int pj  = tx >> 4;                 // pair index 0..7
    const int oj0 = (blockIdx.z << 4) + (pj << 1);  // even output col
    const int oi  = blockIdx.y;
    const int b   = blockIdx.x;              // batch fastest-varying

    const float lam = __ldg(lamb);

    // pool rows / cols (input space)
    const int r0 = 2 * oi - 1;               // may be -1
    const int r1 = 2 * oi;
    const int q0 = 2 * oj0 - 1;              // may be -1
    // q1 = 2*oj0, q2 = 2*oj0+1, q3 = 2*oj0+2  (all >= 0, <= 222)

    // int32 flat indexing: ((b*HH + r)*WW + q)*C4 + c4   (max ~25.7M < 2^31)
    const int bbase = b * (HH * WW * C4);
    const int rowR0 = bbase + r0 * (WW * C4);
    const int rowR1 = bbase + r1 * (WW * C4);
    const int rowS0 = bbase + oi * (WW * C4);        // sel row oi
    const int rowS1 = bbase + (oi + 1) * (WW * C4);  // sel row oi+1

    const bool rv = (oi  > 0);
    const bool qv = (oj0 > 0);
    const float4 z = make_float4(0.f, 0.f, 0.f, 0.f);

    // ---- 13 batched loads (identical order to R6) ----
    float4 a00 = (rv && qv) ? x4[rowR0 + (q0    ) * C4 + c4] : z;
    float4 a01 = rv         ? x4[rowR0 + (q0 + 1) * C4 + c4] : z;
    float4 a02 = rv         ? x4[rowR0 + (q0 + 2) * C4 + c4] : z;
    float4 a03 = rv         ? x4[rowR0 + (q0 + 3) * C4 + c4] : z;
    float4 a10 = qv         ? x4[rowR1 + (q0    ) * C4 + c4] : z;
    float4 a11 =              x4[rowR1 + (q0 + 1) * C4 + c4];
    float4 a12 =              x4[rowR1 + (q0 + 2) * C4 + c4];
    float4 a13 =              x4[rowR1 + (q0 + 3) * C4 + c4];

    // sel taps (always in bounds: rows oi,oi+1 <= 112; cols <= oj0+2 <= 112)
    float4 sL0 = x4[rowS1 + (oj0    ) * C4 + c4];  // l  for pixel 0
    float4 sA0 = x4[rowS1 + (oj0 + 1) * C4 + c4];  // a  for pixel 0, l for pixel 1
    float4 sA1 = x4[rowS1 + (oj0 + 2) * C4 + c4];  // a  for pixel 1
    float4 sU0 = x4[rowS0 + (oj0 + 1) * C4 + c4];  // u  for pixel 0
    float4 sU1 = x4[rowS0 + (oj0 + 2) * C4 + c4];  // u  for pixel 1

    // ---- compute ----
    float4 o0, o1;
    {
        float mx, mn, d;
        // pixel 0, channels x..w
        mx = fmaxf(fmaxf(a00.x, a01.x), fmaxf(a10.x, a11.x));
        mn = ((a00.x + a01.x) + (a10.x + a11.x)) * 0.25f;
        d  = 2.0f * (fabsf(sA0.x - sU0.x) + fabsf(sA0.x - sL0.x));
        o0.x = (d > lam) ? mx : mn;
        mx = fmaxf(fmaxf(a00.y, a01.y), fmaxf(a10.y, a11.y));
        mn = ((a00.y + a01.y) + (a10.y + a11.y)) * 0.25f;
        d  = 2.0f * (fabsf(sA0.y - sU0.y) + fabsf(sA0.y - sL0.y));
        o0.y = (d > lam) ? mx : mn;
        mx = fmaxf(fmaxf(a00.z, a01.z), fmaxf(a10.z, a11.z));
        mn = ((a00.z + a01.z) + (a10.z + a11.z)) * 0.25f;
        d  = 2.0f * (fabsf(sA0.z - sU0.z) + fabsf(sA0.z - sL0.z));
        o0.z = (d > lam) ? mx : mn;
        mx = fmaxf(fmaxf(a00.w, a01.w), fmaxf(a10.w, a11.w));
        mn = ((a00.w + a01.w) + (a10.w + a11.w)) * 0.25f;
        d  = 2.0f * (fabsf(sA0.w - sU0.w) + fabsf(sA0.w - sL0.w));
        o0.w = (d > lam) ? mx : mn;

        // pixel 1, channels x..w  (l tap = sA0)
        mx = fmaxf(fmaxf(a02.x, a03.x), fmaxf(a12.x, a13.x));
        mn = ((a02.x + a03.x) + (a12.x + a13.x)) * 0.25f;
        d  = 2.0f * (fabsf(sA1.x - sU1.x) + fabsf(sA1.x - sA0.x));
        o1.x = (d > lam) ? mx : mn;
        mx = fmaxf(fmaxf(a02.y, a03.y), fmaxf(a12.y, a13.y));
        mn = ((a02.y + a03.y) + (a12.y + a13.y)) * 0.25f;
        d  = 2.0f * (fabsf(sA1.y - sU1.y) + fabsf(sA1.y - sA0.y));
        o1.y = (d > lam) ? mx : mn;
        mx = fmaxf(fmaxf(a02.z, a03.z), fmaxf(a12.z, a13.z));
        mn = ((a02.z + a03.z) + (a12.z + a13.z)) * 0.25f;
        d  = 2.0f * (fabsf(sA1.z - sU1.z) + fabsf(sA1.z - sA0.z));
        o1.z = (d > lam) ? mx : mn;
        mx = fmaxf(fmaxf(a02.w, a03.w), fmaxf(a12.w, a13.w));
        mn = ((a02.w + a03.w) + (a12.w + a13.w)) * 0.25f;
        d  = 2.0f * (fabsf(sA1.w - sU1.w) + fabsf(sA1.w - sA0.w));
        o1.w = (d > lam) ? mx : mn;
    }

    // ---- 2 stores (adjacent pixels, 256B contiguous per 16 lanes) ----
    const int obase = ((b * OH + oi) * OW + oj0) * C4 + c4;
    out4[obase]      = o0;
    out4[obase + C4] = o1;
}

extern "C" void kernel_launch(void* const* d_in, const int* in_sizes, int n_in,
                              void* d_out, int out_size)
{
    const float4* x4   = (const float4*)d_in[0];
    const float*  lamb = (const float*)d_in[1];
    float4*       out4 = (float4*)d_out;

    dim3 grid(BB, OH, OW / 16);   // (32, 112, 7) — batch fastest-varying
    dim3 block(128);              // 16 c4 lanes x 8 oj-pairs
    gradpool_kernel<<<grid, block>>>(x4, lamb, out4);
}

// round 14
// speedup vs baseline: 1.1819x; 1.1819x over previous
#include <cuda_runtime.h>

// GradPooling: fused 2x2 stride-2 max/avg pool gated by local gradient vs lamb.
// x: (32, 224, 224, 64) f32 NHWC ; lamb: (1,) ; out: (32, 112, 112, 64) f32
//
// out[b,oi,oj,c] = sel ? max2x2 : avg2x2 over zero-padded x window
//   window rows {2oi-1, 2oi}, cols {2oj-1, 2oj}  (pad value 0)
// sel = 2*(|a-u| + |a-l|) > lamb, with
//   a = x[b, oi+1, oj+1, c], u = x[b, oi, oj+1, c], l = x[b, oi+1, oj, c]
//
// FINAL (== R2/R6; best: 78.3us harness / 75.9us ncu, DRAM 82.2%).
// DRAM traffic = compulsory floor (~494 MB); achieved BW ~6.5 TB/s is the
// ceiling for this access mix. Falsified alternatives:
//   R3  persistent loop          -> loop issue bubbles (87.1us)
//   R4  evict-first stores       -> L1tex store-path pressure (81.5us)
//   R5  load reorder + maxreg    -> L1tex load-pattern degradation (87.4us)
//   R7  oi-coarsening (y=2)      -> L1tex row mixing (85.4us)
//   R11 4px/thread, block 64     -> too few warps/CTA, occ-limited (80.1us)
//   R13 batch-fastest grid       -> L2 sel-tap locality destroyed, +84MB DRAM (91.1us)
// 2 pixels/thread, natural compile schedule, block 128, grid (oj,oi,b) is the
// roofline configuration.

#define BB 32
#define HH 224
#define WW 224
#define CC 64
#define OH 112
#define OW 112
#define C4 16   // CC/4 float4 lanes per pixel

__global__ __launch_bounds__(128) void gradpool_kernel(
    const float4* __restrict__ x4,
    const float* __restrict__ lamb,
    float4* __restrict__ out4)
{
    const int tx  = threadIdx.x;
    const int c4  = tx & 15;                 // channel float4 lane
    const int pj  = tx >> 4;                 // pair index 0..7
    const int oj0 = (blockIdx.x << 4) + (pj << 1);  // even output col
    const int oi  = blockIdx.y;
    const int b   = blockIdx.z;

    const float lam = __ldg(lamb);

    // pool rows / cols (input space)
    const int r0 = 2 * oi - 1;               // may be -1
    const int r1 = 2 * oi;
    const int q0 = 2 * oj0 - 1;              // may be -1
    // q1 = 2*oj0, q2 = 2*oj0+1, q3 = 2*oj0+2  (all >= 0, <= 222)

    // int32 flat indexing: ((b*HH + r)*WW + q)*C4 + c4   (max ~25.7M < 2^31)
    const int bbase = b * (HH * WW * C4);
    const int rowR0 = bbase + r0 * (WW * C4);
    const int rowR1 = bbase + r1 * (WW * C4);
    const int rowS0 = bbase + oi * (WW * C4);        // sel row oi
    const int rowS1 = bbase + (oi + 1) * (WW * C4);  // sel row oi+1

    const bool rv = (oi  > 0);
    const bool qv = (oj0 > 0);
    const float4 z = make_float4(0.f, 0.f, 0.f, 0.f);

    // ---- 13 batched loads ----
    // pool, pixel 0: cols q0, q0+1 ; pixel 1: cols q0+2, q0+3
    float4 a00 = (rv && qv) ? x4[rowR0 + (q0    ) * C4 + c4] : z;
    float4 a01 = rv         ? x4[rowR0 + (q0 + 1) * C4 + c4] : z;
    float4 a02 = rv         ? x4[rowR0 + (q0 + 2) * C4 + c4] : z;
    float4 a03 = rv         ? x4[rowR0 + (q0 + 3) * C4 + c4] : z;
    float4 a10 = qv         ? x4[rowR1 + (q0    ) * C4 + c4] : z;
    float4 a11 =              x4[rowR1 + (q0 + 1) * C4 + c4];
    float4 a12 =              x4[rowR1 + (q0 + 2) * C4 + c4];
    float4 a13 =              x4[rowR1 + (q0 + 3) * C4 + c4];

    // sel taps (always in bounds: rows oi,oi+1 <= 112; cols <= oj0+2 <= 112)
    float4 sL0 = x4[rowS1 + (oj0    ) * C4 + c4];  // l  for pixel 0
    float4 sA0 = x4[rowS1 + (oj0 + 1) * C4 + c4];  // a  for pixel 0, l for pixel 1
    float4 sA1 = x4[rowS1 + (oj0 + 2) * C4 + c4];  // a  for pixel 1
    float4 sU0 = x4[rowS0 + (oj0 + 1) * C4 + c4];  // u  for pixel 0
    float4 sU1 = x4[rowS0 + (oj0 + 2) * C4 + c4];  // u  for pixel 1

    // ---- compute ----
    float4 o0, o1;
    {
        float mx, mn, d;
        // pixel 0, channels x..w
        mx = fmaxf(fmaxf(a00.x, a01.x), fmaxf(a10.x, a11.x));
        mn = ((a00.x + a01.x) + (a10.x + a11.x)) * 0.25f;
        d  = 2.0f * (fabsf(sA0.x - sU0.x) + fabsf(sA0.x - sL0.x));
        o0.x = (d > lam) ? mx : mn;
        mx = fmaxf(fmaxf(a00.y, a01.y), fmaxf(a10.y, a11.y));
        mn = ((a00.y + a01.y) + (a10.y + a11.y)) * 0.25f;
        d  = 2.0f * (fabsf(sA0.y - sU0.y) + fabsf(sA0.y - sL0.y));
        o0.y = (d > lam) ? mx : mn;
        mx = fmaxf(fmaxf(a00.z, a01.z), fmaxf(a10.z, a11.z));
        mn = ((a00.z + a01.z) + (a10.z + a11.z)) * 0.25f;
        d  = 2.0f * (fabsf(sA0.z - sU0.z) + fabsf(sA0.z - sL0.z));
        o0.z = (d > lam) ? mx : mn;
        mx = fmaxf(fmaxf(a00.w, a01.w), fmaxf(a10.w, a11.w));
        mn = ((a00.w + a01.w) + (a10.w + a11.w)) * 0.25f;
        d  = 2.0f * (fabsf(sA0.w - sU0.w) + fabsf(sA0.w - sL0.w));
        o0.w = (d > lam) ? mx : mn;

        // pixel 1, channels x..w  (l tap = sA0)
        mx = fmaxf(fmaxf(a02.x, a03.x), fmaxf(a12.x, a13.x));
        mn = ((a02.x + a03.x) + (a12.x + a13.x)) * 0.25f;
        d  = 2.0f * (fabsf(sA1.x - sU1.x) + fabsf(sA1.x - sA0.x));
        o1.x = (d > lam) ? mx : mn;
        mx = fmaxf(fmaxf(a02.y, a03.y), fmaxf(a12.y, a13.y));
        mn = ((a02.y + a03.y) + (a12.y + a13.y)) * 0.25f;
        d  = 2.0f * (fabsf(sA1.y - sU1.y) + fabsf(sA1.y - sA0.y));
        o1.y = (d > lam) ? mx : mn;
        mx = fmaxf(fmaxf(a02.z, a03.z), fmaxf(a12.z, a13.z));
        mn = ((a02.z + a03.z) + (a12.z + a13.z)) * 0.25f;
        d  = 2.0f * (fabsf(sA1.z - sU1.z) + fabsf(sA1.z - sA0.z));
        o1.z = (d > lam) ? mx : mn;
        mx = fmaxf(fmaxf(a02.w, a03.w), fmaxf(a12.w, a13.w));
        mn = ((a02.w + a03.w) + (a12.w + a13.w)) * 0.25f;
        d  = 2.0f * (fabsf(sA1.w - sU1.w) + fabsf(sA1.w - sA0.w));
        o1.w = (d > lam) ? mx : mn;
    }

    // ---- 2 stores (adjacent pixels, 256B contiguous per 16 lanes) ----
    const int obase = ((b * OH + oi) * OW + oj0) * C4 + c4;
    out4[obase]      = o0;
    out4[obase + C4] = o1;
}

extern "C" void kernel_launch(void* const* d_in, const int* in_sizes, int n_in,
                              void* d_out, int out_size)
{
    const float4* x4   = (const float4*)d_in[0];
    const float*  lamb = (const float*)d_in[1];
    float4*       out4 = (float4*)d_out;

    dim3 grid(OW / 16, OH, 32);   // (7, 112, 32) — 16 output cols per block
    dim3 block(128);              // 16 c4 lanes x 8 oj-pairs
    gradpool_kernel<<<grid, block>>>(x4, lamb, out4);
}

// round 16
// speedup vs baseline: 1.1868x; 1.0041x over previous
#include <cuda_runtime.h>

// GradPooling: fused 2x2 stride-2 max/avg pool gated by local gradient vs lamb.
// x: (32, 224, 224, 64) f32 NHWC ; lamb: (1,) ; out: (32, 112, 112, 64) f32
//
// out[b,oi,oj,c] = sel ? max2x2 : avg2x2 over zero-padded x window
//   window rows {2oi-1, 2oi}, cols {2oj-1, 2oj}  (pad value 0)
// sel = 2*(|a-u| + |a-l|) > lamb, with
//   a = x[b, oi+1, oj+1, c], u = x[b, oi, oj+1, c], l = x[b, oi+1, oj, c]
//
// FINAL (== R2/R6; 78.3us harness / 75.9us ncu best, 4x reproduced).
// DRAM traffic = compulsory floor (~494 MB); achieved BW ~6.5 TB/s (82% of
// spec) is the ceiling for this access mix on GB300. Falsified alternatives:
//   R3  persistent loop          -> loop issue bubbles (87.1us)
//   R4  evict-first stores       -> L1tex store-path pressure (81.5us)
//   R5  load reorder + maxreg    -> L1tex load-pattern degradation (87.4us)
//   R7  oi-coarsening (y=2)      -> L1tex row mixing (85.4us)
//   R11 4px/thread, block 64     -> too few warps/CTA (80.1us)
//   R13 batch-fastest grid       -> L2 sel-tap locality lost, +84MB DRAM (91.1us)
// 2 pixels/thread, natural compile schedule, block 128, grid (oj,oi,b).

#define BB 32
#define HH 224
#define WW 224
#define CC 64
#define OH 112
#define OW 112
#define C4 16   // CC/4 float4 lanes per pixel

__global__ __launch_bounds__(128) void gradpool_kernel(
    const float4* __restrict__ x4,
    const float* __restrict__ lamb,
    float4* __restrict__ out4)
{
    const int tx  = threadIdx.x;
    const int c4  = tx & 15;                 // channel float4 lane
    const int pj  = tx >> 4;                 // pair index 0..7
    const int oj0 = (blockIdx.x << 4) + (pj << 1);  // even output col
    const int oi  = blockIdx.y;
    const int b   = blockIdx.z;

    const float lam = __ldg(lamb);

    // pool rows / cols (input space)
    const int r0 = 2 * oi - 1;               // may be -1
    const int r1 = 2 * oi;
    const int q0 = 2 * oj0 - 1;              // may be -1
    // q1 = 2*oj0, q2 = 2*oj0+1, q3 = 2*oj0+2  (all >= 0, <= 222)

    // int32 flat indexing: ((b*HH + r)*WW + q)*C4 + c4   (max ~25.7M < 2^31)
    const int bbase = b * (HH * WW * C4);
    const int rowR0 = bbase + r0 * (WW * C4);
    const int rowR1 = bbase + r1 * (WW * C4);
    const int rowS0 = bbase + oi * (WW * C4);        // sel row oi
    const int rowS1 = bbase + (oi + 1) * (WW * C4);  // sel row oi+1

    const bool rv = (oi  > 0);
    const bool qv = (oj0 > 0);
    const float4 z = make_float4(0.f, 0.f, 0.f, 0.f);

    // ---- 13 batched loads ----
    // pool, pixel 0: cols q0, q0+1 ; pixel 1: cols q0+2, q0+3
    float4 a00 = (rv && qv) ? x4[rowR0 + (q0    ) * C4 + c4] : z;
    float4 a01 = rv         ? x4[rowR0 + (q0 + 1) * C4 + c4] : z;
    float4 a02 = rv         ? x4[rowR0 + (q0 + 2) * C4 + c4] : z;
    float4 a03 = rv         ? x4[rowR0 + (q0 + 3) * C4 + c4] : z;
    float4 a10 = qv         ? x4[rowR1 + (q0    ) * C4 + c4] : z;
    float4 a11 =              x4[rowR1 + (q0 + 1) * C4 + c4];
    float4 a12 =              x4[rowR1 + (q0 + 2) * C4 + c4];
    float4 a13 =              x4[rowR1 + (q0 + 3) * C4 + c4];

    // sel taps (always in bounds: rows oi,oi+1 <= 112; cols <= oj0+2 <= 112)
    float4 sL0 = x4[rowS1 + (oj0    ) * C4 + c4];  // l  for pixel 0
    float4 sA0 = x4[rowS1 + (oj0 + 1) * C4 + c4];  // a  for pixel 0, l for pixel 1
    float4 sA1 = x4[rowS1 + (oj0 + 2) * C4 + c4];  // a  for pixel 1
    float4 sU0 = x4[rowS0 + (oj0 + 1) * C4 + c4];  // u  for pixel 0
    float4 sU1 = x4[rowS0 + (oj0 + 2) * C4 + c4];  // u  for pixel 1

    // ---- compute ----
    float4 o0, o1;
    {
        float mx, mn, d;
        // pixel 0, channels x..w
        mx = fmaxf(fmaxf(a00.x, a01.x), fmaxf(a10.x, a11.x));
        mn = ((a00.x + a01.x) + (a10.x + a11.x)) * 0.25f;
        d  = 2.0f * (fabsf(sA0.x - sU0.x) + fabsf(sA0.x - sL0.x));
        o0.x = (d > lam) ? mx : mn;
        mx = fmaxf(fmaxf(a00.y, a01.y), fmaxf(a10.y, a11.y));
        mn = ((a00.y + a01.y) + (a10.y + a11.y)) * 0.25f;
        d  = 2.0f * (fabsf(sA0.y - sU0.y) + fabsf(sA0.y - sL0.y));
        o0.y = (d > lam) ? mx : mn;
        mx = fmaxf(fmaxf(a00.z, a01.z), fmaxf(a10.z, a11.z));
        mn = ((a00.z + a01.z) + (a10.z + a11.z)) * 0.25f;
        d  = 2.0f * (fabsf(sA0.z - sU0.z) + fabsf(sA0.z - sL0.z));
        o0.z = (d > lam) ? mx : mn;
        mx = fmaxf(fmaxf(a00.w, a01.w), fmaxf(a10.w, a11.w));
        mn = ((a00.w + a01.w) + (a10.w + a11.w)) * 0.25f;
        d  = 2.0f * (fabsf(sA0.w - sU0.w) + fabsf(sA0.w - sL0.w));
        o0.w = (d > lam) ? mx : mn;

        // pixel 1, channels x..w  (l tap = sA0)
        mx = fmaxf(fmaxf(a02.x, a03.x), fmaxf(a12.x, a13.x));
        mn = ((a02.x + a03.x) + (a12.x + a13.x)) * 0.25f;
        d  = 2.0f * (fabsf(sA1.x - sU1.x) + fabsf(sA1.x - sA0.x));
        o1.x = (d > lam) ? mx : mn;
        mx = fmaxf(fmaxf(a02.y, a03.y), fmaxf(a12.y, a13.y));
        mn = ((a02.y + a03.y) + (a12.y + a13.y)) * 0.25f;
        d  = 2.0f * (fabsf(sA1.y - sU1.y) + fabsf(sA1.y - sA0.y));
        o1.y = (d > lam) ? mx : mn;
        mx = fmaxf(fmaxf(a02.z, a03.z), fmaxf(a12.z, a13.z));
        mn = ((a02.z + a03.z) + (a12.z + a13.z)) * 0.25f;
        d  = 2.0f * (fabsf(sA1.z - sU1.z) + fabsf(sA1.z - sA0.z));
        o1.z = (d > lam) ? mx : mn;
        mx = fmaxf(fmaxf(a02.w, a03.w), fmaxf(a12.w, a13.w));
        mn = ((a02.w + a03.w) + (a12.w + a13.w)) * 0.25f;
        d  = 2.0f * (fabsf(sA1.w - sU1.w) + fabsf(sA1.w - sA0.w));
        o1.w = (d > lam) ? mx : mn;
    }

    // ---- 2 stores (adjacent pixels, 256B contiguous per 16 lanes) ----
    const int obase = ((b * OH + oi) * OW + oj0) * C4 + c4;
    out4[obase]      = o0;
    out4[obase + C4] = o1;
}

extern "C" void kernel_launch(void* const* d_in, const int* in_sizes, int n_in,
                              void* d_out, int out_size)
{
    const float4* x4   = (const float4*)d_in[0];
    const float*  lamb = (const float*)d_in[1];
    float4*       out4 = (float4*)d_out;

    dim3 grid(OW / 16, OH, 32);   // (7, 112, 32) — 16 output cols per block
    dim3 block(128);              // 16 c4 lanes x 8 oj-pairs
    gradpool_kernel<<<grid, block>>>(x4, lamb, out4);
}